// round 15
// baseline (speedup 1.0000x reference)
#include <cuda_runtime.h>
#include <cstdint>
#include <math.h>

// SoftmaxSetAttention, GB300 (plain sm_103 target). Round 15: round-14
// (fp16-global K/V pre-pass, fp16 mma + ldmatrix, producer softmax, D-split
// consumers, BC=64, 2 CTAs/SM) with DECOUPLED producer/consumer sync:
// split named barriers (PF/PE handshake on the double-buffered P exchange,
// per-group barriers for K/V stage reuse) replace the two full-block
// bar.syncs, letting A and B skew by a full tile and hide each other's
// dependency tails.  Numerics identical to rounds 12-14.

#define BATCH 2
#define HEADS 16
#define LQ 2048
#define LK 2048
#define DD 128
#define BR 64
#define BC 64
#define NKT 32
#define NTHREADS 256
#define PADF 132

#define KROW     272u
#define KSTG16   17408u        // 64 keys x 272 B
#define K16_OFF  0u            // 2 stages = 34816
#define V16_OFF  34816u        // 3 stages -> 87040
#define P_OFF    87040u        // 2 buffers x 128 chunks x 80 B
#define PCH      80u
#define PBUF     10240u
#define LM_OFF   107520u       // float lm[2][64]
#define LINV_OFF 108032u       // float linv[64]
#define SMEM_BYTES 108288u     // x2 CTAs = 216576 <= 227328

__device__ uint4 K16g[(size_t)BATCH * HEADS * LK * DD / 8];
__device__ uint4 V16g[(size_t)BATCH * HEADS * LK * DD / 8];

__device__ __forceinline__ float ex2f(float x) {
    float r; asm("ex2.approx.ftz.f32 %0, %1;" : "=f"(r) : "f"(x)); return r;
}
__device__ __forceinline__ uint32_t packh(float hi, float lo) {
    uint32_t r; asm("cvt.rn.f16x2.f32 %0, %1, %2;" : "=r"(r) : "f"(hi), "f"(lo));
    return r;
}
__device__ __forceinline__ void mma16(float* c, const uint32_t* a, uint32_t b0, uint32_t b1) {
    asm volatile(
        "mma.sync.aligned.m16n8k16.row.col.f32.f16.f16.f32 "
        "{%0,%1,%2,%3}, {%4,%5,%6,%7}, {%8,%9}, {%0,%1,%2,%3};"
        : "+f"(c[0]), "+f"(c[1]), "+f"(c[2]), "+f"(c[3])
        : "r"(a[0]), "r"(a[1]), "r"(a[2]), "r"(a[3]), "r"(b0), "r"(b1));
}
__device__ __forceinline__ void cp16(uint32_t dst, const void* src) {
    asm volatile("cp.async.cg.shared.global [%0], [%1], 16;" :: "r"(dst), "l"(src));
}
#define CP_COMMIT()  asm volatile("cp.async.commit_group;" ::: "memory")
#define CP_WAIT0()   asm volatile("cp.async.wait_group 0;" ::: "memory")
#define BSYNC(id, n) asm volatile("bar.sync %0, %1;" :: "r"(id), "r"(n) : "memory")
#define BARR(id, n)  asm volatile("bar.arrive %0, %1;" :: "r"(id), "r"(n) : "memory")
#define STS128(a, v0, v1, v2, v3) \
    asm volatile("st.shared.v4.b32 [%0], {%1, %2, %3, %4};" \
                 :: "r"(a), "r"(v0), "r"(v1), "r"(v2), "r"(v3) : "memory")
#define LDS128U(v0, v1, v2, v3, a) \
    asm volatile("ld.shared.v4.b32 {%0, %1, %2, %3}, [%4];" \
                 : "=r"(v0), "=r"(v1), "=r"(v2), "=r"(v3) : "r"(a))
#define LDSM4(r0, r1, r2, r3, a) \
    asm volatile("ldmatrix.sync.aligned.m8n8.x4.shared.b16 {%0,%1,%2,%3}, [%4];" \
                 : "=r"(r0), "=r"(r1), "=r"(r2), "=r"(r3) : "r"(a))
#define LDSM4T(r0, r1, r2, r3, a) \
    asm volatile("ldmatrix.sync.aligned.m8n8.x4.trans.shared.b16 {%0,%1,%2,%3}, [%4];" \
                 : "=r"(r0), "=r"(r1), "=r"(r2), "=r"(r3) : "r"(a))

// barrier ids: 1=final linv, 2=A-group, 3=B-group, 4/5=PF0/PF1, 6/7=PE0/PE1

// ---- pre-pass: fp32 -> fp16 ----
__global__ void __launch_bounds__(256, 8)
cvt16_kernel(const float4* __restrict__ srcK, const float4* __restrict__ srcV)
{
    const size_t i = (size_t)blockIdx.x * 256 + threadIdx.x;
    const float4* src = blockIdx.y ? srcV : srcK;
    uint4* dst = blockIdx.y ? V16g : K16g;
    float4 a = src[2 * i], b2 = src[2 * i + 1];
    uint4 r;
    r.x = packh(a.y, a.x);   r.y = packh(a.w, a.z);
    r.z = packh(b2.y, b2.x); r.w = packh(b2.w, b2.z);
    dst[i] = r;
}

__global__ void __launch_bounds__(NTHREADS, 2)
ssa_dec_kernel(const float* __restrict__ Q, const int* __restrict__ MULT,
               float* __restrict__ O)
{
    extern __shared__ float smem[];
    const uint32_t sb = (uint32_t)__cvta_generic_to_shared(smem);

    const int tid  = threadIdx.x;
    const int lane = tid & 31;
    const int g    = lane >> 2;
    const int tq   = lane & 3;
    const int bh   = blockIdx.y;
    const int qt   = blockIdx.x;
    const int b    = bh / HEADS;

    const float* Qp = Q + ((size_t)bh * LQ + (size_t)qt * BR) * DD;
    const char*  Kg = (const char*)K16g + (size_t)bh * LK * 256;
    const char*  Vg = (const char*)V16g + (size_t)bh * LK * 256;
    const int*   Mp = MULT + (size_t)b * LK;
    float*       Op = O + ((size_t)bh * LQ + (size_t)qt * BR) * DD;

    const float scale2 = 1.4426950408889634f / 11.313708498984760f;
    const float FIXMAX = 16.0f;

    // ---- prologue: stage Q (PAD-132 fp32) at smem bytes [0, 33792) ----
    #pragma unroll
    for (int i = 0; i < 8; i++) {
        int idx = tid + i * NTHREADS;
        int row = idx >> 5, dc = idx & 31;
        cp16(sb + (uint32_t)(row * PADF + dc * 4) * 4u, Qp + (size_t)row * DD + dc * 4);
    }
    CP_COMMIT();
    CP_WAIT0();
    __syncthreads();

    if (tid < 128) {
        // ===== GROUP A: S = Q K^T (64 keys), softmax, publish fp16 P, own l =====
        const int wa = tid >> 5;
        uint32_t qa[8][4];
        {
            const float* q0 = smem + (wa * 16 + g) * PADF;
            const float* q1 = q0 + 8 * PADF;
            #pragma unroll
            for (int ks = 0; ks < 8; ks++) {
                const int d = ks * 16 + 2 * tq;
                qa[ks][0] = packh(q0[d + 1], q0[d]);
                qa[ks][1] = packh(q1[d + 1], q1[d]);
                qa[ks][2] = packh(q0[d + 9], q0[d + 8]);
                qa[ks][3] = packh(q1[d + 9], q1[d + 8]);
            }
        }
        __syncthreads();                        // Q consumed; K stages writable

        float mv = 1.0f;
        if (tid < BC) mv = (float)Mp[tid];

        // K(0): cp.async fp16 tile into stage 0
        #pragma unroll
        for (int j = 0; j < 8; j++) {
            int idx = tid + j * 128;
            int row = idx >> 4, c = idx & 15;
            cp16(sb + K16_OFF + (uint32_t)(row * (int)KROW + c * 16),
                 Kg + (size_t)row * 256 + c * 16);
        }
        CP_COMMIT();

        float l_r[2] = {0.f, 0.f};
        const uint32_t pst = sb + P_OFF + (uint32_t)tid * PCH;
        const int o_t = lane >> 3, o_r = lane & 7;
        const uint32_t ka0 = sb + K16_OFF +
            (uint32_t)((8 * (o_t >> 1) + o_r) * (int)KROW + (o_t & 1) * 16);

        #pragma unroll 1
        for (int i = 0; i < NKT; i++) {
            // lm(i) into buffer i&1; prefetch mv(i+1)
            if (tid < BC) smem[LM_OFF / 4 + (i & 1) * BC + tid] = __log2f(mv) - FIXMAX;
            if (i + 1 < NKT && tid < BC) mv = (float)Mp[(size_t)(i + 1) * BC + tid];

            CP_WAIT0();                         // K(i) landed
            BSYNC(2, 128);                      // A-group: K-stage reuse + lm visible
            if (i + 1 < NKT) {                  // issue K(i+1) -> stage (i+1)&1
                const uint32_t kd = sb + K16_OFF + (uint32_t)(((i + 1) & 1) ? KSTG16 : 0u);
                const char* kg = Kg + (size_t)(i + 1) * BC * 256;
                #pragma unroll
                for (int j = 0; j < 8; j++) {
                    int idx = tid + j * 128;
                    int row = idx >> 4, c = idx & 15;
                    cp16(kd + (uint32_t)(row * (int)KROW + c * 16),
                         kg + (size_t)row * 256 + c * 16);
                }
            }
            CP_COMMIT();

            // S = Q K^T on K(i)
            const uint32_t ka = ka0 + (uint32_t)((i & 1) ? KSTG16 : 0u);
            float sc[8][4];
            #pragma unroll
            for (int n = 0; n < 8; n++)
                { sc[n][0]=0.f; sc[n][1]=0.f; sc[n][2]=0.f; sc[n][3]=0.f; }
            #pragma unroll
            for (int ks = 0; ks < 8; ks++) {
                #pragma unroll
                for (int p = 0; p < 4; p++) {
                    uint32_t b0, b1, b2, b3;
                    LDSM4(b0, b1, b2, b3, ka + (uint32_t)(p * 4352) + 32u * ks);
                    mma16(sc[2 * p],     qa[ks], b0, b1);
                    mma16(sc[2 * p + 1], qa[ks], b2, b3);
                }
            }
            // softmax in place
            const float* lmp = smem + LM_OFF / 4 + (i & 1) * BC;
            #pragma unroll
            for (int n = 0; n < 8; n++) {
                const float lA = lmp[n * 8 + 2 * tq];
                const float lB = lmp[n * 8 + 2 * tq + 1];
                sc[n][0] = ex2f(fmaf(sc[n][0], scale2, lA));
                sc[n][1] = ex2f(fmaf(sc[n][1], scale2, lB));
                sc[n][2] = ex2f(fmaf(sc[n][2], scale2, lA));
                sc[n][3] = ex2f(fmaf(sc[n][3], scale2, lB));
                l_r[0] += sc[n][0] + sc[n][1];
                l_r[1] += sc[n][2] + sc[n][3];
            }
            uint32_t pk[16];
            #pragma unroll
            for (int ksg = 0; ksg < 4; ksg++) {
                pk[ksg * 4 + 0] = packh(sc[2*ksg][1],   sc[2*ksg][0]);
                pk[ksg * 4 + 1] = packh(sc[2*ksg][3],   sc[2*ksg][2]);
                pk[ksg * 4 + 2] = packh(sc[2*ksg+1][1], sc[2*ksg+1][0]);
                pk[ksg * 4 + 3] = packh(sc[2*ksg+1][3], sc[2*ksg+1][2]);
            }

            if (i >= 2) BSYNC(6 + (i & 1), 256);   // wait P buffer i&1 free
            const uint32_t pb = pst + (uint32_t)((i & 1) ? PBUF : 0u);
            STS128(pb,       pk[0],  pk[1],  pk[2],  pk[3]);
            STS128(pb + 16u, pk[4],  pk[5],  pk[6],  pk[7]);
            STS128(pb + 32u, pk[8],  pk[9],  pk[10], pk[11]);
            STS128(pb + 48u, pk[12], pk[13], pk[14], pk[15]);
            BARR(4 + (i & 1), 256);                // P(i) full
        }

        // epilogue A: row normalizers -> smem, then release B
        float lt0 = l_r[0];
        lt0 += __shfl_xor_sync(0xffffffffu, lt0, 1);
        lt0 += __shfl_xor_sync(0xffffffffu, lt0, 2);
        float lt1 = l_r[1];
        lt1 += __shfl_xor_sync(0xffffffffu, lt1, 1);
        lt1 += __shfl_xor_sync(0xffffffffu, lt1, 2);
        if (tq == 0) {
            smem[LINV_OFF / 4 + wa * 16 + g]     = __fdividef(1.0f, lt0);
            smem[LINV_OFF / 4 + wa * 16 + g + 8] = __fdividef(1.0f, lt1);
        }
        BSYNC(1, 256);
    } else {
        // ===== GROUP B: warp wb owns D-chunk [32wb,32wb+32) for all 64 rows =====
        const int tb = tid - 128;
        const int wb = tb >> 5;
        __syncthreads();                        // matches A's post-frag sync

        // V(0): cp.async fp16 tile into stage 0
        #pragma unroll
        for (int j = 0; j < 8; j++) {
            int idx = tb + j * 128;
            int row = idx >> 4, c = idx & 15;
            cp16(sb + V16_OFF + (uint32_t)(row * (int)KROW + c * 16),
                 Vg + (size_t)row * 256 + c * 16);
        }
        CP_COMMIT();

        float o[4][4][4];
        #pragma unroll
        for (int mt = 0; mt < 4; mt++)
            #pragma unroll
            for (int nt = 0; nt < 4; nt++)
                { o[mt][nt][0]=0.f; o[mt][nt][1]=0.f; o[mt][nt][2]=0.f; o[mt][nt][3]=0.f; }

        const int v_t = lane >> 3, v_r = lane & 7;
        const uint32_t va0 = sb + V16_OFF +
            (uint32_t)((8 * (v_t & 1) + v_r) * (int)KROW + (v_t >> 1) * 16 + wb * 64);

        #pragma unroll 1
        for (int i = 0; i < NKT; i++) {
            CP_WAIT0();                         // V(i) landed
            BSYNC(3, 128);                      // B-group: V-stage reuse
            if (i + 1 < NKT) {                  // issue V(i+1) -> stage (i+1)%3
                const uint32_t vd = sb + V16_OFF + (uint32_t)(((i + 1) % 3) * (int)KSTG16);
                const char* vg = Vg + (size_t)(i + 1) * BC * 256;
                #pragma unroll
                for (int j = 0; j < 8; j++) {
                    int idx = tb + j * 128;
                    int row = idx >> 4, c = idx & 15;
                    cp16(vd + (uint32_t)(row * (int)KROW + c * 16),
                         vg + (size_t)row * 256 + c * 16);
                }
            }
            CP_COMMIT();

            BSYNC(4 + (i & 1), 256);            // wait P(i) full
            uint32_t pa[4][16];                 // [mt][ksg*4+j]
            {
                const uint32_t pbuf = sb + P_OFF +
                    (uint32_t)((i & 1) ? PBUF : 0u) + (uint32_t)lane * PCH;
                #pragma unroll
                for (int mt = 0; mt < 4; mt++) {
                    #pragma unroll
                    for (int ksg = 0; ksg < 4; ksg++)
                        LDS128U(pa[mt][ksg*4+0], pa[mt][ksg*4+1],
                                pa[mt][ksg*4+2], pa[mt][ksg*4+3],
                                pbuf + (uint32_t)(mt * 32) * PCH + (uint32_t)(ksg * 16));
                }
            }
            if (i < NKT - 2) BARR(6 + (i & 1), 256);   // P buffer i&1 free

            const uint32_t va = va0 + (uint32_t)((i % 3) * (int)KSTG16);
            #pragma unroll
            for (int ksg = 0; ksg < 4; ksg++) {
                #pragma unroll
                for (int jj = 0; jj < 2; jj++) {
                    uint32_t b0, b1, b2, b3;
                    LDSM4T(b0, b1, b2, b3, va + (uint32_t)(ksg * 4352) + 32u * jj);
                    #pragma unroll
                    for (int mt = 0; mt < 4; mt++) {
                        mma16(o[mt][2 * jj],     &pa[mt][ksg * 4], b0, b1);
                        mma16(o[mt][2 * jj + 1], &pa[mt][ksg * 4], b2, b3);
                    }
                }
            }
        }

        BSYNC(1, 256);
        // epilogue B: normalize with A's linv, store D-chunk for all rows
        #pragma unroll
        for (int mt = 0; mt < 4; mt++) {
            const float inv0 = smem[LINV_OFF / 4 + mt * 16 + g];
            const float inv1 = smem[LINV_OFF / 4 + mt * 16 + g + 8];
            float* o0 = Op + (size_t)(mt * 16 + g) * DD + wb * 32 + 2 * tq;
            float* o1 = Op + (size_t)(mt * 16 + g + 8) * DD + wb * 32 + 2 * tq;
            #pragma unroll
            for (int nt = 0; nt < 4; nt++) {
                float2 v0 = make_float2(o[mt][nt][0] * inv0, o[mt][nt][1] * inv0);
                float2 v1 = make_float2(o[mt][nt][2] * inv1, o[mt][nt][3] * inv1);
                *(float2*)(o0 + nt * 8) = v0;
                *(float2*)(o1 + nt * 8) = v1;
            }
        }
    }
}

extern "C" void kernel_launch(void* const* d_in, const int* in_sizes, int n_in,
                              void* d_out, int out_size)
{
    const float* Q = (const float*)d_in[0];
    const float* K = (const float*)d_in[1];
    const float* V = (const float*)d_in[2];
    const int*   M = (const int*)d_in[3];
    float*       O = (float*)d_out;

    {
        dim3 cg((unsigned)((size_t)BATCH * HEADS * LK * DD / 8 / 256), 2);
        cvt16_kernel<<<cg, 256>>>((const float4*)K, (const float4*)V);
    }

    cudaFuncSetAttribute(ssa_dec_kernel,
                         cudaFuncAttributeMaxDynamicSharedMemorySize, SMEM_BYTES);
    dim3 grid(LQ / BR, BATCH * HEADS);
    ssa_dec_kernel<<<grid, NTHREADS, SMEM_BYTES>>>(Q, M, O);
}

// round 16
// speedup vs baseline: 1.1963x; 1.1963x over previous
#include <cuda_runtime.h>
#include <cstdint>
#include <math.h>

// SoftmaxSetAttention, GB300 (plain sm_103 target). Round 16: round 14
// (best: fp16-global K/V pre-pass, fp16 mma + ldmatrix, producer softmax,
// D-split consumers, BC=64, lockstep 2-barrier pipeline, 2 CTAs/SM) plus
// software-pipelined operand fetch: ldmatrix/LDS results double-buffered in
// registers one step ahead of their consuming mma, removing exposed
// smem->tensor latency. Numerics identical (rel_err bit-identical).

#define BATCH 2
#define HEADS 16
#define LQ 2048
#define LK 2048
#define DD 128
#define BR 64
#define BC 64
#define NKT 32
#define NTHREADS 256
#define PADF 132

#define KROW     272u
#define KSTG16   17408u        // 64 keys x 272 B
#define K16_OFF  0u            // 2 stages = 34816
#define V16_OFF  34816u        // 3 stages -> 87040
#define P_OFF    87040u        // 2 buffers x 128 chunks x 80 B
#define PCH      80u
#define PBUF     10240u
#define LM_OFF   107520u       // float lm[64]
#define LINV_OFF 107776u       // float linv[64]
#define SMEM_BYTES 108032u     // x2 CTAs = 216064 <= 227328

__device__ uint4 K16g[(size_t)BATCH * HEADS * LK * DD / 8];
__device__ uint4 V16g[(size_t)BATCH * HEADS * LK * DD / 8];

__device__ __forceinline__ float ex2f(float x) {
    float r; asm("ex2.approx.ftz.f32 %0, %1;" : "=f"(r) : "f"(x)); return r;
}
__device__ __forceinline__ uint32_t packh(float hi, float lo) {
    uint32_t r; asm("cvt.rn.f16x2.f32 %0, %1, %2;" : "=r"(r) : "f"(hi), "f"(lo));
    return r;
}
__device__ __forceinline__ void mma16(float* c, const uint32_t* a, uint32_t b0, uint32_t b1) {
    asm volatile(
        "mma.sync.aligned.m16n8k16.row.col.f32.f16.f16.f32 "
        "{%0,%1,%2,%3}, {%4,%5,%6,%7}, {%8,%9}, {%0,%1,%2,%3};"
        : "+f"(c[0]), "+f"(c[1]), "+f"(c[2]), "+f"(c[3])
        : "r"(a[0]), "r"(a[1]), "r"(a[2]), "r"(a[3]), "r"(b0), "r"(b1));
}
__device__ __forceinline__ void cp16(uint32_t dst, const void* src) {
    asm volatile("cp.async.cg.shared.global [%0], [%1], 16;" :: "r"(dst), "l"(src));
}
#define CP_COMMIT() asm volatile("cp.async.commit_group;" ::: "memory")
#define CP_WAIT(n)  asm volatile("cp.async.wait_group %0;" :: "n"(n) : "memory")
#define BAR(id)     asm volatile("bar.sync %0, %1;" :: "r"(id), "r"(NTHREADS) : "memory")
#define STS128(a, v0, v1, v2, v3) \
    asm volatile("st.shared.v4.b32 [%0], {%1, %2, %3, %4};" \
                 :: "r"(a), "r"(v0), "r"(v1), "r"(v2), "r"(v3) : "memory")
#define LDS128U(v0, v1, v2, v3, a) \
    asm volatile("ld.shared.v4.b32 {%0, %1, %2, %3}, [%4];" \
                 : "=r"(v0), "=r"(v1), "=r"(v2), "=r"(v3) : "r"(a))
#define LDSM4(r0, r1, r2, r3, a) \
    asm volatile("ldmatrix.sync.aligned.m8n8.x4.shared.b16 {%0,%1,%2,%3}, [%4];" \
                 : "=r"(r0), "=r"(r1), "=r"(r2), "=r"(r3) : "r"(a))
#define LDSM4T(r0, r1, r2, r3, a) \
    asm volatile("ldmatrix.sync.aligned.m8n8.x4.trans.shared.b16 {%0,%1,%2,%3}, [%4];" \
                 : "=r"(r0), "=r"(r1), "=r"(r2), "=r"(r3) : "r"(a))

// ---- pre-pass: fp32 -> fp16 ----
__global__ void __launch_bounds__(256, 8)
cvt16_kernel(const float4* __restrict__ srcK, const float4* __restrict__ srcV)
{
    const size_t i = (size_t)blockIdx.x * 256 + threadIdx.x;
    const float4* src = blockIdx.y ? srcV : srcK;
    uint4* dst = blockIdx.y ? V16g : K16g;
    float4 a = src[2 * i], b2 = src[2 * i + 1];
    uint4 r;
    r.x = packh(a.y, a.x);   r.y = packh(a.w, a.z);
    r.z = packh(b2.y, b2.x); r.w = packh(b2.w, b2.z);
    dst[i] = r;
}

__global__ void __launch_bounds__(NTHREADS, 2)
ssa_pf16_kernel(const float* __restrict__ Q, const int* __restrict__ MULT,
                float* __restrict__ O)
{
    extern __shared__ float smem[];
    const uint32_t sb = (uint32_t)__cvta_generic_to_shared(smem);

    const int tid  = threadIdx.x;
    const int lane = tid & 31;
    const int g    = lane >> 2;
    const int tq   = lane & 3;
    const int bh   = blockIdx.y;
    const int qt   = blockIdx.x;
    const int b    = bh / HEADS;

    const float* Qp = Q + ((size_t)bh * LQ + (size_t)qt * BR) * DD;
    const char*  Kg = (const char*)K16g + (size_t)bh * LK * 256;
    const char*  Vg = (const char*)V16g + (size_t)bh * LK * 256;
    const int*   Mp = MULT + (size_t)b * LK;
    float*       Op = O + ((size_t)bh * LQ + (size_t)qt * BR) * DD;

    const float scale2 = 1.4426950408889634f / 11.313708498984760f;
    const float FIXMAX = 16.0f;

    // ---- prologue: stage Q (PAD-132 fp32) at smem bytes [0, 33792) ----
    #pragma unroll
    for (int i = 0; i < 8; i++) {
        int idx = tid + i * NTHREADS;
        int row = idx >> 5, dc = idx & 31;
        cp16(sb + (uint32_t)(row * PADF + dc * 4) * 4u, Qp + (size_t)row * DD + dc * 4);
    }
    CP_COMMIT();
    CP_WAIT(0);
    __syncthreads();

    if (tid < 128) {
        // ===== GROUP A: S = Q K^T (64 keys), softmax, publish fp16 P, own l =====
        const int wa = tid >> 5;
        uint32_t qa[8][4];
        {
            const float* q0 = smem + (wa * 16 + g) * PADF;
            const float* q1 = q0 + 8 * PADF;
            #pragma unroll
            for (int ks = 0; ks < 8; ks++) {
                const int d = ks * 16 + 2 * tq;
                qa[ks][0] = packh(q0[d + 1], q0[d]);
                qa[ks][1] = packh(q1[d + 1], q1[d]);
                qa[ks][2] = packh(q0[d + 9], q0[d + 8]);
                qa[ks][3] = packh(q1[d + 9], q1[d + 8]);
            }
        }
        __syncthreads();

        float mv = 1.0f;
        if (tid < BC) mv = (float)Mp[tid];

        // K(0): cp.async fp16 tile into stage 0
        #pragma unroll
        for (int j = 0; j < 8; j++) {
            int idx = tid + j * 128;
            int row = idx >> 4, c = idx & 15;
            cp16(sb + K16_OFF + (uint32_t)(row * (int)KROW + c * 16),
                 Kg + (size_t)row * 256 + c * 16);
        }
        CP_COMMIT();

        float l_r[2] = {0.f, 0.f};
        const uint32_t pst = sb + P_OFF + (uint32_t)tid * PCH;
        const int o_t = lane >> 3, o_r = lane & 7;
        const uint32_t ka0 = sb + K16_OFF +
            (uint32_t)((8 * (o_t >> 1) + o_r) * (int)KROW + (o_t & 1) * 16);

        #pragma unroll 1
        for (int i = 0; i <= NKT; i++) {
            if (i + 1 < NKT) {                  // issue K(i+1)
                const uint32_t kd = sb + K16_OFF + (uint32_t)(((i + 1) & 1) ? KSTG16 : 0u);
                const char* kg = Kg + (size_t)(i + 1) * BC * 256;
                #pragma unroll
                for (int j = 0; j < 8; j++) {
                    int idx = tid + j * 128;
                    int row = idx >> 4, c = idx & 15;
                    cp16(kd + (uint32_t)(row * (int)KROW + c * 16),
                         kg + (size_t)row * 256 + c * 16);
                }
            }
            CP_COMMIT();
            if (i < NKT && tid < BC)
                smem[LM_OFF / 4 + tid] = __log2f(mv) - FIXMAX;
            if (i + 1 < NKT && tid < BC) mv = (float)Mp[(size_t)(i + 1) * BC + tid];
            CP_WAIT(1);
            BAR(1);

            uint32_t pk[16];
            if (i < NKT) {
                const uint32_t ka = ka0 + (uint32_t)((i & 1) ? KSTG16 : 0u);
                float sc[8][4];
                #pragma unroll
                for (int n = 0; n < 8; n++)
                    { sc[n][0]=0.f; sc[n][1]=0.f; sc[n][2]=0.f; sc[n][3]=0.f; }

                // software-pipelined ldsm: step t -> (ks = t>>2, p = t&3)
                uint32_t kb[2][4];
                LDSM4(kb[0][0], kb[0][1], kb[0][2], kb[0][3], ka);
                #pragma unroll
                for (int t = 0; t < 32; t++) {
                    if (t + 1 < 32) {
                        const int ks2 = (t + 1) >> 2, p2 = (t + 1) & 3;
                        LDSM4(kb[(t + 1) & 1][0], kb[(t + 1) & 1][1],
                              kb[(t + 1) & 1][2], kb[(t + 1) & 1][3],
                              ka + (uint32_t)(p2 * 4352) + 32u * (uint32_t)ks2);
                    }
                    const int ks = t >> 2, p = t & 3;
                    mma16(sc[2 * p],     qa[ks], kb[t & 1][0], kb[t & 1][1]);
                    mma16(sc[2 * p + 1], qa[ks], kb[t & 1][2], kb[t & 1][3]);
                }
                // softmax in place
                const float* lmp = smem + LM_OFF / 4;
                #pragma unroll
                for (int n = 0; n < 8; n++) {
                    const float lA = lmp[n * 8 + 2 * tq];
                    const float lB = lmp[n * 8 + 2 * tq + 1];
                    sc[n][0] = ex2f(fmaf(sc[n][0], scale2, lA));
                    sc[n][1] = ex2f(fmaf(sc[n][1], scale2, lB));
                    sc[n][2] = ex2f(fmaf(sc[n][2], scale2, lA));
                    sc[n][3] = ex2f(fmaf(sc[n][3], scale2, lB));
                    l_r[0] += sc[n][0] + sc[n][1];
                    l_r[1] += sc[n][2] + sc[n][3];
                }
                #pragma unroll
                for (int ksg = 0; ksg < 4; ksg++) {
                    pk[ksg * 4 + 0] = packh(sc[2*ksg][1],   sc[2*ksg][0]);
                    pk[ksg * 4 + 1] = packh(sc[2*ksg][3],   sc[2*ksg][2]);
                    pk[ksg * 4 + 2] = packh(sc[2*ksg+1][1], sc[2*ksg+1][0]);
                    pk[ksg * 4 + 3] = packh(sc[2*ksg+1][3], sc[2*ksg+1][2]);
                }
            }
            BAR(2);
            if (i < NKT) {                      // publish P(i) into buffer i&1
                const uint32_t pb = pst + (uint32_t)((i & 1) ? PBUF : 0u);
                STS128(pb,       pk[0],  pk[1],  pk[2],  pk[3]);
                STS128(pb + 16u, pk[4],  pk[5],  pk[6],  pk[7]);
                STS128(pb + 32u, pk[8],  pk[9],  pk[10], pk[11]);
                STS128(pb + 48u, pk[12], pk[13], pk[14], pk[15]);
            }
        }

        // epilogue A: row normalizers -> smem
        float lt0 = l_r[0];
        lt0 += __shfl_xor_sync(0xffffffffu, lt0, 1);
        lt0 += __shfl_xor_sync(0xffffffffu, lt0, 2);
        float lt1 = l_r[1];
        lt1 += __shfl_xor_sync(0xffffffffu, lt1, 1);
        lt1 += __shfl_xor_sync(0xffffffffu, lt1, 2);
        if (tq == 0) {
            smem[LINV_OFF / 4 + wa * 16 + g]     = __fdividef(1.0f, lt0);
            smem[LINV_OFF / 4 + wa * 16 + g + 8] = __fdividef(1.0f, lt1);
        }
        BAR(3);
    } else {
        // ===== GROUP B: warp wb owns D-chunk [32wb,32wb+32) for all 64 rows =====
        const int tb = tid - 128;
        const int wb = tb >> 5;
        __syncthreads();

        // V(0): cp.async fp16 tile into stage 0
        #pragma unroll
        for (int j = 0; j < 8; j++) {
            int idx = tb + j * 128;
            int row = idx >> 4, c = idx & 15;
            cp16(sb + V16_OFF + (uint32_t)(row * (int)KROW + c * 16),
                 Vg + (size_t)row * 256 + c * 16);
        }
        CP_COMMIT();

        float o[4][4][4];
        #pragma unroll
        for (int mt = 0; mt < 4; mt++)
            #pragma unroll
            for (int nt = 0; nt < 4; nt++)
                { o[mt][nt][0]=0.f; o[mt][nt][1]=0.f; o[mt][nt][2]=0.f; o[mt][nt][3]=0.f; }

        const int v_t = lane >> 3, v_r = lane & 7;
        const uint32_t va0 = sb + V16_OFF +
            (uint32_t)((8 * (v_t & 1) + v_r) * (int)KROW + (v_t >> 1) * 16 + wb * 64);

        #pragma unroll 1
        for (int i = 0; i <= NKT; i++) {
            if (i + 1 < NKT) {                  // issue V(i+1) -> stage (i+1)%3
                const uint32_t vd = sb + V16_OFF + (uint32_t)(((i + 1) % 3) * (int)KSTG16);
                const char* vg = Vg + (size_t)(i + 1) * BC * 256;
                #pragma unroll
                for (int j = 0; j < 8; j++) {
                    int idx = tb + j * 128;
                    int row = idx >> 4, c = idx & 15;
                    cp16(vd + (uint32_t)(row * (int)KROW + c * 16),
                         vg + (size_t)row * 256 + c * 16);
                }
            }
            CP_COMMIT();
            CP_WAIT(2);
            BAR(1);

            if (i >= 1) {
                const uint32_t pbuf = sb + P_OFF +
                    (uint32_t)(((i - 1) & 1) ? PBUF : 0u) + (uint32_t)lane * PCH;
                const uint32_t va = va0 + (uint32_t)(((i - 1) % 3) * (int)KSTG16);

                // prefetch pa(ksg=0) and first V ldsm
                uint32_t pa[2][4][4];
                #pragma unroll
                for (int mt = 0; mt < 4; mt++)
                    LDS128U(pa[0][mt][0], pa[0][mt][1], pa[0][mt][2], pa[0][mt][3],
                            pbuf + (uint32_t)(mt * 32) * PCH);
                uint32_t vb[2][4];
                LDSM4T(vb[0][0], vb[0][1], vb[0][2], vb[0][3], va);

                #pragma unroll
                for (int t = 0; t < 8; t++) {   // t = ksg*2 + jj
                    const int ksg = t >> 1, jj = t & 1;
                    if (t + 1 < 8) {
                        const int ksg2 = (t + 1) >> 1, jj2 = (t + 1) & 1;
                        LDSM4T(vb[(t + 1) & 1][0], vb[(t + 1) & 1][1],
                               vb[(t + 1) & 1][2], vb[(t + 1) & 1][3],
                               va + (uint32_t)(ksg2 * 4352) + 32u * (uint32_t)jj2);
                        if (jj2 == 0) {         // prefetch pa for next ksg
                            #pragma unroll
                            for (int mt = 0; mt < 4; mt++)
                                LDS128U(pa[ksg2 & 1][mt][0], pa[ksg2 & 1][mt][1],
                                        pa[ksg2 & 1][mt][2], pa[ksg2 & 1][mt][3],
                                        pbuf + (uint32_t)(mt * 32) * PCH +
                                        (uint32_t)(ksg2 * 16));
                        }
                    }
                    #pragma unroll
                    for (int mt = 0; mt < 4; mt++) {
                        mma16(o[mt][2 * jj],     pa[ksg & 1][mt], vb[t & 1][0], vb[t & 1][1]);
                        mma16(o[mt][2 * jj + 1], pa[ksg & 1][mt], vb[t & 1][2], vb[t & 1][3]);
                    }
                }
            }
            BAR(2);
        }

        BAR(3);
        // epilogue B: normalize with A's linv, store D-chunk for all rows
        #pragma unroll
        for (int mt = 0; mt < 4; mt++) {
            const float inv0 = smem[LINV_OFF / 4 + mt * 16 + g];
            const float inv1 = smem[LINV_OFF / 4 + mt * 16 + g + 8];
            float* o0 = Op + (size_t)(mt * 16 + g) * DD + wb * 32 + 2 * tq;
            float* o1 = Op + (size_t)(mt * 16 + g + 8) * DD + wb * 32 + 2 * tq;
            #pragma unroll
            for (int nt = 0; nt < 4; nt++) {
                float2 v0 = make_float2(o[mt][nt][0] * inv0, o[mt][nt][1] * inv0);
                float2 v1 = make_float2(o[mt][nt][2] * inv1, o[mt][nt][3] * inv1);
                *(float2*)(o0 + nt * 8) = v0;
                *(float2*)(o1 + nt * 8) = v1;
            }
        }
    }
}

extern "C" void kernel_launch(void* const* d_in, const int* in_sizes, int n_in,
                              void* d_out, int out_size)
{
    const float* Q = (const float*)d_in[0];
    const float* K = (const float*)d_in[1];
    const float* V = (const float*)d_in[2];
    const int*   M = (const int*)d_in[3];
    float*       O = (float*)d_out;

    {
        dim3 cg((unsigned)((size_t)BATCH * HEADS * LK * DD / 8 / 256), 2);
        cvt16_kernel<<<cg, 256>>>((const float4*)K, (const float4*)V);
    }

    cudaFuncSetAttribute(ssa_pf16_kernel,
                         cudaFuncAttributeMaxDynamicSharedMemorySize, SMEM_BYTES);
    dim3 grid(LQ / BR, BATCH * HEADS);
    ssa_pf16_kernel<<<grid, NTHREADS, SMEM_BYTES>>>(Q, M, O);
}